// round 1
// baseline (speedup 1.0000x reference)
#include <cuda_runtime.h>
#include <cstdint>
#include <cstddef>

#define Bx 4
#define Vx 64
#define Ex 1024
#define Lx 1024
#define Dx 256
#define DEGx 16

// Packed dual-fp32 FMA (Blackwell f32x2): c += a*b elementwise on packed pairs.
__device__ __forceinline__ void ffma2(unsigned long long &c,
                                      unsigned long long a,
                                      unsigned long long b) {
    asm("fma.rn.f32x2 %0, %1, %2, %0;" : "+l"(c) : "l"(a), "l"(b));
}

// One CTA per (b, l). 256 threads = 8 warps.
// smem: Xs[64][256] | Wt4[8][256] float4 (k-packed, xor-swizzled) | Qs[64][256] | Ks[64][256]
__global__ __launch_bounds__(256, 1)
void edge_learner_fused(const float* __restrict__ hs,
                        const int*   __restrict__ edge_index,
                        const float* __restrict__ edge_weight,
                        const float* __restrict__ Wq, const float* __restrict__ bq,
                        const float* __restrict__ Wk, const float* __restrict__ bk,
                        const float* __restrict__ attn_skip_p,
                        float* __restrict__ out)
{
    extern __shared__ float sm[];
    float* Xs = sm;                         // 16384 floats
    float* Wt = sm + 16384;                 // 8192 floats (8*256 float4)
    float* Qs = sm + 16384 + 8192;          // 16384 floats
    float* Ks = Qs + 16384;                 // 16384 floats

    const int bx = blockIdx.x;
    const int b  = bx >> 10;
    const int l  = bx & 1023;
    const int t  = threadIdx.x;
    const int w  = t >> 5;
    const int j  = t & 31;

    // ---- Part 1: fill a 2048-float slice of the broadcast ei output ----
    {
        const int base = bx * 2048;
        #pragma unroll
        for (int r = 0; r < 8; r++) {
            int idx = base + r * 256 + t;
            out[idx] = (float)edge_index[idx >> 10];   // ei[c,e,l] = edge_index[c,e]
        }
    }

    // ---- Part 2: stage X = hs[b, :, l, :] into smem (coalesced float4) ----
    {
        const int k4 = t & 63;          // float4 index in row
        const int vo = t >> 6;          // 0..3
        #pragma unroll
        for (int it = 0; it < 16; it++) {
            int v = it * 4 + vo;
            const float4 val = *(const float4*)(hs
                + (size_t)(b * Vx + v) * (Lx * Dx) + (size_t)l * Dx + k4 * 4);
            *(float4*)(Xs + v * 256 + k4 * 4) = val;
        }
    }

    float4* Wt4 = (float4*)Wt;

    // ---- Part 3: Q and K GEMMs (64x256 @ 256x256^T), f32x2 packed over k ----
    #pragma unroll 1
    for (int mat = 0; mat < 2; mat++) {
        const float*  Wg   = mat ? Wk : Wq;
        const float*  bg   = mat ? bk : bq;
        float*        Outs = mat ? Ks : Qs;
        const float4* Wg4  = (const float4*)Wg;

        unsigned long long acc[8][8];
        #pragma unroll
        for (int ii = 0; ii < 8; ii++)
            #pragma unroll
            for (int jj = 0; jj < 8; jj++) acc[ii][jj] = 0ull;

        #pragma unroll 1
        for (int kt = 0; kt < 8; kt++) {
            __syncthreads();
            // stage W chunk: Wt4[kk][d ^ kk] = W[d][kt*32 + kk*4 .. +3]
            #pragma unroll
            for (int it = 0; it < 8; it++) {
                int idx = it * 256 + t;
                int d   = idx >> 3;
                int kk  = idx & 7;
                Wt4[kk * 256 + (d ^ kk)] = Wg4[d * 64 + kt * 8 + kk];
            }
            __syncthreads();

            #pragma unroll
            for (int kk = 0; kk < 8; kk++) {
                ulonglong2 xv[8];
                #pragma unroll
                for (int ii = 0; ii < 8; ii++)   // warp-broadcast (conflict-free)
                    xv[ii] = *(const ulonglong2*)(Xs + (w * 8 + ii) * 256 + kt * 32 + kk * 4);
                #pragma unroll
                for (int jj = 0; jj < 8; jj++) {
                    int d = j + 32 * jj;        // lanes consecutive -> conflict-free
                    ulonglong2 wv = *(const ulonglong2*)(Wt + (kk * 256 + (d ^ kk)) * 4);
                    #pragma unroll
                    for (int ii = 0; ii < 8; ii++) {
                        ffma2(acc[ii][jj], xv[ii].x, wv.x);
                        ffma2(acc[ii][jj], xv[ii].y, wv.y);
                    }
                }
            }
        }

        // write result + bias to smem
        #pragma unroll
        for (int jj = 0; jj < 8; jj++) {
            int d = j + 32 * jj;
            float bias = bg[d];
            #pragma unroll
            for (int ii = 0; ii < 8; ii++) {
                float lo = __uint_as_float((unsigned)(acc[ii][jj]));
                float hi = __uint_as_float((unsigned)(acc[ii][jj] >> 32));
                Outs[(w * 8 + ii) * 256 + d] = lo + hi + bias;
            }
        }
    }
    __syncthreads();

    // ---- Part 4: per-src 16-neighbor attention + softmax + output ----
    const float skip = attn_skip_p[0];
    float* outEw = out + (size_t)2 * Bx * Ex * Lx;
    const int* srcIdx = edge_index;             // row 0
    const int* dstIdx = edge_index + Bx * Ex;   // row 1

    #pragma unroll 1
    for (int s8 = 0; s8 < 8; s8++) {
        const int vq    = w * 8 + s8;
        const int ebase = b * Ex + vq * DEGx;
        const int srcv  = srcIdx[ebase];        // == vq by construction

        // lane j owns d in [4j,4j+4) and [128+4j,128+4j+4)  (conflict-free float4)
        const float4 qa = *(const float4*)(Qs + srcv * 256 + 4 * j);
        const float4 qb = *(const float4*)(Qs + srcv * 256 + 128 + 4 * j);

        float sc[16];
        #pragma unroll
        for (int tt = 0; tt < 16; tt++) {
            const int dst = dstIdx[ebase + tt];
            const float4 ka = *(const float4*)(Ks + dst * 256 + 4 * j);
            const float4 kb = *(const float4*)(Ks + dst * 256 + 128 + 4 * j);
            float p = qa.x * ka.x + qa.y * ka.y + qa.z * ka.z + qa.w * ka.w
                    + qb.x * kb.x + qb.y * kb.y + qb.z * kb.z + qb.w * kb.w;
            #pragma unroll
            for (int off = 16; off > 0; off >>= 1)
                p += __shfl_xor_sync(0xffffffffu, p, off);
            sc[tt] = p * 0.0625f;               // / sqrt(256)
        }

        float m = sc[0];
        #pragma unroll
        for (int tt = 1; tt < 16; tt++) m = fmaxf(m, sc[tt]);
        float ex[16];
        float Z = 0.0f;
        #pragma unroll
        for (int tt = 0; tt < 16; tt++) { ex[tt] = __expf(sc[tt] - m); Z += ex[tt]; }
        const float sca = (1.0f - skip) / Z;

        #pragma unroll
        for (int tt = 0; tt < 16; tt++) {
            if (j == tt) {
                const int ge = ebase + tt;
                outEw[(size_t)ge * Lx + l] = skip * edge_weight[ge] + sca * ex[tt];
            }
        }
    }
}

extern "C" void kernel_launch(void* const* d_in, const int* in_sizes, int n_in,
                              void* d_out, int out_size)
{
    const float* hs  = (const float*)d_in[0];
    const int*   ei  = (const int*)  d_in[1];
    const float* ew  = (const float*)d_in[2];
    const float* Wq  = (const float*)d_in[3];
    const float* bq  = (const float*)d_in[4];
    const float* Wk  = (const float*)d_in[5];
    const float* bk  = (const float*)d_in[6];
    const float* sk  = (const float*)d_in[7];
    float* out = (float*)d_out;

    const int smem_bytes = (16384 + 8192 + 16384 + 16384) * 4;   // 229376 B
    cudaFuncSetAttribute(edge_learner_fused,
                         cudaFuncAttributeMaxDynamicSharedMemorySize, smem_bytes);

    edge_learner_fused<<<Bx * Lx, 256, smem_bytes>>>(hs, ei, ew, Wq, bq, Wk, bk, sk, out);
}

// round 4
// speedup vs baseline: 3.6400x; 3.6400x over previous
#include <cuda_runtime.h>
#include <cstdint>
#include <cstddef>

#define Bx 4
#define Vx 64
#define Ex 1024
#define Lx 1024
#define Dx 256

#define XSTR 260   // Xs/Zs row stride (floats)
#define WSTR 36    // Ws row stride

// Precomputed per-launch operator:  M[k][n] = sum_c Wq[c][k]*Wk[c][n]  stored as Mt[n][k] (tf32-rounded)
__device__ float g_Mt[256 * 256];
__device__ float g_u[256];     // u[k] = sum_c Wq[c][k]*bk[c]
__device__ float g_r[256];     // r[n] = sum_c bq[c]*Wk[c][n]
__device__ float g_c0;         // bq . bk

__device__ __forceinline__ float tf32r(float x) {
    unsigned u; asm("cvt.rna.tf32.f32 %0, %1;" : "=r"(u) : "f"(x));
    return __uint_as_float(u);
}

__device__ __forceinline__ void mma_tf32(float (&d)[4], const unsigned (&a)[4],
                                         unsigned b0, unsigned b1) {
    asm volatile("mma.sync.aligned.m16n8k8.row.col.f32.tf32.tf32.f32 "
                 "{%0,%1,%2,%3}, {%4,%5,%6,%7}, {%8,%9}, {%0,%1,%2,%3};"
                 : "+f"(d[0]), "+f"(d[1]), "+f"(d[2]), "+f"(d[3])
                 : "r"(a[0]), "r"(a[1]), "r"(a[2]), "r"(a[3]), "r"(b0), "r"(b1));
}

// ---------------- precompute: Mt[n][k] = M[k][n] = (Wq^T Wk)[k][n], u, r, c0 ----------------
__global__ void precompute_kernel(const float* __restrict__ Wq, const float* __restrict__ bq,
                                  const float* __restrict__ Wk, const float* __restrict__ bk)
{
    __shared__ float sWk[256];
    __shared__ float red[256];
    const int n = blockIdx.x, j = threadIdx.x;
    sWk[j] = Wk[j * 256 + n];
    __syncthreads();
    float acc = 0.f, uacc = 0.f;
    #pragma unroll 4
    for (int d = 0; d < 256; d++) {
        float wq = Wq[d * 256 + j];
        acc = fmaf(wq, sWk[d], acc);
        if (n == 0) uacc = fmaf(wq, __ldg(bk + d), uacc);
    }
    g_Mt[n * 256 + j] = tf32r(acc);
    if (n == 0) g_u[j] = uacc;
    red[j] = bq[j] * sWk[j];
    __syncthreads();
    for (int s = 128; s > 0; s >>= 1) { if (j < s) red[j] += red[j + s]; __syncthreads(); }
    if (j == 0) g_r[n] = red[0];
    if (n == 0) {
        red[j] = bq[j] * __ldg(bk + j);
        __syncthreads();
        for (int s = 128; s > 0; s >>= 1) { if (j < s) red[j] += red[j + s]; __syncthreads(); }
        if (j == 0) g_c0 = red[0];
    }
}

// ---------------- main: one CTA per (b,l) ----------------
__global__ __launch_bounds__(256, 1)
void edge_learner_main(const float* __restrict__ hs,
                       const int*   __restrict__ edge_index,
                       const float* __restrict__ edge_weight,
                       const float* __restrict__ attn_skip_p,
                       float* __restrict__ out)
{
    extern __shared__ float sm[];
    float* Xs  = sm;                     // 64*260
    float* Zs  = Xs + 64 * XSTR;         // 64*260
    float* Ws0 = Zs + 64 * XSTR;         // 256*36
    float* Ws1 = Ws0 + 256 * WSTR;       // 256*36
    float* Su  = Ws1 + 256 * WSTR;       // 256
    float* Sr  = Su + 256;               // 256
    float* Sa  = Sr + 256;               // 64
    float* Sc  = Sa + 64;                // 64
    int*   Sd  = (int*)(Sc + 64);        // 1024
    float* Sew = (float*)(Sd + 1024);    // 1024

    const int bx = blockIdx.x;
    const int b = bx >> 10, l = bx & 1023;
    const int t = threadIdx.x, w = t >> 5, j = t & 31;

    // prefetch W chunk 0 (k columns 0..31) via cp.async
    {
        #pragma unroll
        for (int i = 0; i < 8; i++) {
            int idx = i * 256 + t, n = idx >> 3, q = idx & 7;
            unsigned d = (unsigned)__cvta_generic_to_shared(Ws0 + n * WSTR + q * 4);
            asm volatile("cp.async.ca.shared.global [%0], [%1], 16;"
                         :: "r"(d), "l"(g_Mt + n * 256 + q * 4));
        }
        asm volatile("cp.async.commit_group;" ::: "memory");
    }

    // ---- ei output fill (broadcast of edge_index over L) ----
    {
        const int base = bx * 2048;
        #pragma unroll
        for (int r = 0; r < 8; r++) {
            int idx = base + r * 256 + t;
            out[idx] = (float)edge_index[idx >> 10];
        }
    }

    // ---- stage X = hs[b,:,l,:] (tf32-rounded) ----
    {
        const int k4 = t & 63, vo = t >> 6;
        #pragma unroll
        for (int it = 0; it < 16; it++) {
            int v = it * 4 + vo;
            float4 val = *(const float4*)(hs + (size_t)(b * Vx + v) * (Lx * Dx)
                                             + (size_t)l * Dx + k4 * 4);
            val.x = tf32r(val.x); val.y = tf32r(val.y);
            val.z = tf32r(val.z); val.w = tf32r(val.w);
            *(float4*)(Xs + v * XSTR + k4 * 4) = val;
        }
    }
    // stage u, r, dst list, edge weights
    Su[t] = g_u[t];
    Sr[t] = g_r[t];
    {
        const int*   dsts = edge_index + Bx * Ex + b * Ex;
        const float* ews  = edge_weight + b * Ex;
        #pragma unroll
        for (int i = 0; i < 4; i++) {
            Sd[i * 256 + t]  = dsts[i * 256 + t];
            Sew[i * 256 + t] = ews[i * 256 + t];
        }
    }
    __syncthreads();

    // ---- per-vertex bias dots: Sa[v] = X_v.u , Sc[v] = X_v.r ----
    {
        const float4 ua = ((const float4*)Su)[j];
        const float4 ub = ((const float4*)Su)[32 + j];
        const float4 ra = ((const float4*)Sr)[j];
        const float4 rb = ((const float4*)Sr)[32 + j];
        #pragma unroll
        for (int s = 0; s < 8; s++) {
            int v = w * 8 + s;
            float4 xa = *(const float4*)(Xs + v * XSTR + 4 * j);
            float4 xb = *(const float4*)(Xs + v * XSTR + 128 + 4 * j);
            float pa = xa.x*ua.x + xa.y*ua.y + xa.z*ua.z + xa.w*ua.w
                     + xb.x*ub.x + xb.y*ub.y + xb.z*ub.z + xb.w*ub.w;
            float pc = xa.x*ra.x + xa.y*ra.y + xa.z*ra.z + xa.w*ra.w
                     + xb.x*rb.x + xb.y*rb.y + xb.z*rb.z + xb.w*rb.w;
            #pragma unroll
            for (int off = 16; off > 0; off >>= 1) {
                pa += __shfl_xor_sync(~0u, pa, off);
                pc += __shfl_xor_sync(~0u, pc, off);
            }
            if (j == 0) { Sa[v] = pa; Sc[v] = pc; }
        }
    }

    // ---- GEMM: Z[64][256] = X @ Mt^T  (Z[v][n] = sum_k X[v][k] M[k][n]) ----
    float acc[2][8][4];
    #pragma unroll
    for (int a = 0; a < 2; a++)
        #pragma unroll
        for (int c = 0; c < 8; c++)
            #pragma unroll
            for (int q = 0; q < 4; q++) acc[a][c][q] = 0.f;

    const int mb = (w & 1) * 32;
    const int nb = (w >> 1) * 64;
    const int rA = j >> 2, cA = j & 3;

    #pragma unroll 1
    for (int kt = 0; kt < 8; kt++) {
        if (kt < 7) {
            float* Wn = (kt & 1) ? Ws0 : Ws1;            // buffer for chunk kt+1
            const float* src = g_Mt + (kt + 1) * 32;
            #pragma unroll
            for (int i = 0; i < 8; i++) {
                int idx = i * 256 + t, n = idx >> 3, q = idx & 7;
                unsigned d = (unsigned)__cvta_generic_to_shared(Wn + n * WSTR + q * 4);
                asm volatile("cp.async.ca.shared.global [%0], [%1], 16;"
                             :: "r"(d), "l"(src + n * 256 + q * 4));
            }
            asm volatile("cp.async.commit_group;" ::: "memory");
            asm volatile("cp.async.wait_group 1;" ::: "memory");
        } else {
            asm volatile("cp.async.wait_group 0;" ::: "memory");
        }
        __syncthreads();
        const float* W = (kt & 1) ? Ws1 : Ws0;

        #pragma unroll
        for (int ks = 0; ks < 4; ks++) {
            const int kc = kt * 32 + ks * 8;
            unsigned a[2][4];
            #pragma unroll
            for (int mt = 0; mt < 2; mt++) {
                const float* xp = Xs + (mb + mt * 16 + rA) * XSTR + kc + cA;
                a[mt][0] = __float_as_uint(xp[0]);
                a[mt][1] = __float_as_uint(xp[8 * XSTR]);
                a[mt][2] = __float_as_uint(xp[4]);
                a[mt][3] = __float_as_uint(xp[8 * XSTR + 4]);
            }
            #pragma unroll
            for (int nt = 0; nt < 8; nt++) {
                const float* wp = W + (nb + nt * 8 + rA) * WSTR + ks * 8 + cA;
                unsigned b0 = __float_as_uint(wp[0]);
                unsigned b1 = __float_as_uint(wp[4]);
                mma_tf32(acc[0][nt], a[0], b0, b1);
                mma_tf32(acc[1][nt], a[1], b0, b1);
            }
        }
        __syncthreads();
    }

    // ---- epilogue: Z to smem ----
    #pragma unroll
    for (int mt = 0; mt < 2; mt++)
        #pragma unroll
        for (int nt = 0; nt < 8; nt++) {
            int row = mb + mt * 16 + rA;
            int col = nb + nt * 8 + 2 * cA;
            *(float2*)(Zs + row * XSTR + col)       = make_float2(acc[mt][nt][0], acc[mt][nt][1]);
            *(float2*)(Zs + (row + 8) * XSTR + col) = make_float2(acc[mt][nt][2], acc[mt][nt][3]);
        }
    __syncthreads();

    // ---- attention: logit(v,dst) = (Z_v.X_dst + Sa[v] + Sc[dst] + c0)/16 ----
    // NOTE: q-vector from Zs (= x_v M), k-vector from Xs (= x_dst). This gives
    // x_v M x_dst^T (M is NOT symmetric — reading the other way was the R2 bug).
    const float skip = attn_skip_p[0];
    const float c0 = g_c0;
    float* outEw = out + (size_t)2 * Bx * Ex * Lx;

    #pragma unroll 1
    for (int s = 0; s < 8; s++) {
        const int v = w * 8 + s;
        const float4 qa = *(const float4*)(Zs + v * XSTR + 4 * j);
        const float4 qb = *(const float4*)(Zs + v * XSTR + 128 + 4 * j);
        float p[16];
        #pragma unroll
        for (int tt = 0; tt < 16; tt++) {
            const int dst = Sd[v * 16 + tt];
            const float4 ka = *(const float4*)(Xs + dst * XSTR + 4 * j);
            const float4 kb = *(const float4*)(Xs + dst * XSTR + 128 + 4 * j);
            p[tt] = qa.x*ka.x + qa.y*ka.y + qa.z*ka.z + qa.w*ka.w
                  + qb.x*kb.x + qb.y*kb.y + qb.z*kb.z + qb.w*kb.w;
        }
        // 16-value butterfly transpose-reduce: value tt lands (full 32-lane sum) on lanes 2tt,2tt+1
        #pragma unroll
        for (int i = 0; i < 8; i++) {
            float lo = (j & 16) ? p[i + 8] : p[i];
            float hv = (j & 16) ? p[i] : p[i + 8];
            p[i] = lo + __shfl_xor_sync(~0u, hv, 16);
        }
        #pragma unroll
        for (int i = 0; i < 4; i++) {
            float lo = (j & 8) ? p[i + 4] : p[i];
            float hv = (j & 8) ? p[i] : p[i + 4];
            p[i] = lo + __shfl_xor_sync(~0u, hv, 8);
        }
        #pragma unroll
        for (int i = 0; i < 2; i++) {
            float lo = (j & 4) ? p[i + 2] : p[i];
            float hv = (j & 4) ? p[i] : p[i + 2];
            p[i] = lo + __shfl_xor_sync(~0u, hv, 4);
        }
        {
            float lo = (j & 2) ? p[1] : p[0];
            float hv = (j & 2) ? p[0] : p[1];
            p[0] = lo + __shfl_xor_sync(~0u, hv, 2);
        }
        p[0] += __shfl_xor_sync(~0u, p[0], 1);

        const int tt = (j >> 1) & 15;
        const int dst = Sd[v * 16 + tt];
        float sc = (p[0] + Sa[v] + Sc[dst] + c0) * 0.0625f;

        float m = sc;
        #pragma unroll
        for (int off = 16; off > 0; off >>= 1) m = fmaxf(m, __shfl_xor_sync(~0u, m, off));
        float e = __expf(sc - m);
        float Zt = e;
        #pragma unroll
        for (int off = 16; off > 0; off >>= 1) Zt += __shfl_xor_sync(~0u, Zt, off);
        Zt *= 0.5f;   // each tt counted twice (duplicate lanes)

        if (!(j & 1)) {
            const int ge = b * Ex + v * 16 + tt;
            outEw[(size_t)ge * Lx + l] = skip * Sew[v * 16 + tt] + (1.0f - skip) / Zt * e;
        }
    }
}

extern "C" void kernel_launch(void* const* d_in, const int* in_sizes, int n_in,
                              void* d_out, int out_size)
{
    const float* hs = (const float*)d_in[0];
    const int*   ei = (const int*)  d_in[1];
    const float* ew = (const float*)d_in[2];
    const float* Wq = (const float*)d_in[3];
    const float* bq = (const float*)d_in[4];
    const float* Wk = (const float*)d_in[5];
    const float* bk = (const float*)d_in[6];
    const float* sk = (const float*)d_in[7];
    float* out = (float*)d_out;

    precompute_kernel<<<256, 256>>>(Wq, bq, Wk, bk);

    const int smem_bytes = (64 * XSTR * 2 + 256 * WSTR * 2 + 256 + 256 + 64 + 64 + 1024 + 1024) * 4;
    cudaFuncSetAttribute(edge_learner_main,
                         cudaFuncAttributeMaxDynamicSharedMemorySize, smem_bytes);
    edge_learner_main<<<Bx * Lx, 256, smem_bytes>>>(hs, ei, ew, sk, out);
}

// round 5
// speedup vs baseline: 4.5689x; 1.2552x over previous
#include <cuda_runtime.h>
#include <cstdint>
#include <cstddef>

#define Bx 4
#define Vx 64
#define Ex 1024
#define Lx 1024
#define Dx 256

#define XSTR 260   // Xs/Zs row stride (floats)
#define WSTR 36    // Ws row stride
#define SSTR 68    // Ss row stride

// Precomputed per-launch operator:  M[k][n] = sum_c Wq[c][k]*Wk[c][n]  stored as Mt[n][k] (tf32-rounded)
__device__ float g_Mt[256 * 256];
__device__ float g_u[256];     // u[k] = sum_c Wq[c][k]*bk[c]
__device__ float g_r[256];     // r[n] = sum_c bq[c]*Wk[c][n]
__device__ float g_c0;         // bq . bk

__device__ __forceinline__ float tf32r(float x) {
    unsigned u; asm("cvt.rna.tf32.f32 %0, %1;" : "=r"(u) : "f"(x));
    return __uint_as_float(u);
}

__device__ __forceinline__ void mma_tf32(float (&d)[4], const unsigned (&a)[4],
                                         unsigned b0, unsigned b1) {
    asm volatile("mma.sync.aligned.m16n8k8.row.col.f32.tf32.tf32.f32 "
                 "{%0,%1,%2,%3}, {%4,%5,%6,%7}, {%8,%9}, {%0,%1,%2,%3};"
                 : "+f"(d[0]), "+f"(d[1]), "+f"(d[2]), "+f"(d[3])
                 : "r"(a[0]), "r"(a[1]), "r"(a[2]), "r"(a[3]), "r"(b0), "r"(b1));
}

// ---------------- precompute: Mt[n][k] = M[k][n] = (Wq^T Wk)[k][n], u, r, c0 ----------------
__global__ void precompute_kernel(const float* __restrict__ Wq, const float* __restrict__ bq,
                                  const float* __restrict__ Wk, const float* __restrict__ bk)
{
    __shared__ float sWk[256];
    __shared__ float red[256];
    const int n = blockIdx.x, j = threadIdx.x;
    sWk[j] = Wk[j * 256 + n];
    __syncthreads();
    float acc = 0.f, uacc = 0.f;
    #pragma unroll 4
    for (int d = 0; d < 256; d++) {
        float wq = Wq[d * 256 + j];
        acc = fmaf(wq, sWk[d], acc);
        if (n == 0) uacc = fmaf(wq, __ldg(bk + d), uacc);
    }
    g_Mt[n * 256 + j] = tf32r(acc);
    if (n == 0) g_u[j] = uacc;
    red[j] = bq[j] * sWk[j];
    __syncthreads();
    for (int s = 128; s > 0; s >>= 1) { if (j < s) red[j] += red[j + s]; __syncthreads(); }
    if (j == 0) g_r[n] = red[0];
    if (n == 0) {
        red[j] = bq[j] * __ldg(bk + j);
        __syncthreads();
        for (int s = 128; s > 0; s >>= 1) { if (j < s) red[j] += red[j + s]; __syncthreads(); }
        if (j == 0) g_c0 = red[0];
    }
}

// ---------------- main: one CTA per (b,l) ----------------
__global__ __launch_bounds__(256, 1)
void edge_learner_main(const float* __restrict__ hs,
                       const int*   __restrict__ edge_index,
                       const float* __restrict__ edge_weight,
                       const float* __restrict__ attn_skip_p,
                       float* __restrict__ out)
{
    extern __shared__ float sm[];
    float* Xs  = sm;                     // 64*260
    float* Zs  = Xs + 64 * XSTR;         // 64*260
    float* Ws0 = Zs + 64 * XSTR;         // 256*36
    float* Ws1 = Ws0 + 256 * WSTR;       // 256*36
    float* Su  = Ws1 + 256 * WSTR;       // 256
    float* Sr  = Su + 256;               // 256
    float* Sa  = Sr + 256;               // 64
    float* Sc  = Sa + 64;                // 64
    int*   Sd  = (int*)(Sc + 64);        // 1024
    float* Sew = (float*)(Sd + 1024);    // 1024
    // S score buffers overlay the (dead-after-GEMM) Ws double buffers
    float* Ss0 = Ws0;                    // 64*68 partial (k half 0)
    float* Ss1 = Ws0 + 64 * SSTR;        // 64*68 partial (k half 1)

    const int bx = blockIdx.x;
    const int b = bx >> 10, l = bx & 1023;
    const int t = threadIdx.x, w = t >> 5, j = t & 31;

    // prefetch W chunk 0 (k columns 0..31) via cp.async
    {
        #pragma unroll
        for (int i = 0; i < 8; i++) {
            int idx = i * 256 + t, n = idx >> 3, q = idx & 7;
            unsigned d = (unsigned)__cvta_generic_to_shared(Ws0 + n * WSTR + q * 4);
            asm volatile("cp.async.ca.shared.global [%0], [%1], 16;"
                         :: "r"(d), "l"(g_Mt + n * 256 + q * 4));
        }
        asm volatile("cp.async.commit_group;" ::: "memory");
    }

    // ---- ei output fill (broadcast of edge_index over L) ----
    {
        const int base = bx * 2048;
        #pragma unroll
        for (int r = 0; r < 8; r++) {
            int idx = base + r * 256 + t;
            out[idx] = (float)edge_index[idx >> 10];
        }
    }

    // ---- stage X = hs[b,:,l,:] (tf32-rounded) ----
    {
        const int k4 = t & 63, vo = t >> 6;
        #pragma unroll
        for (int it = 0; it < 16; it++) {
            int v = it * 4 + vo;
            float4 val = *(const float4*)(hs + (size_t)(b * Vx + v) * (Lx * Dx)
                                             + (size_t)l * Dx + k4 * 4);
            val.x = tf32r(val.x); val.y = tf32r(val.y);
            val.z = tf32r(val.z); val.w = tf32r(val.w);
            *(float4*)(Xs + v * XSTR + k4 * 4) = val;
        }
    }
    // stage u, r, dst list, edge weights
    Su[t] = g_u[t];
    Sr[t] = g_r[t];
    {
        const int*   dsts = edge_index + Bx * Ex + b * Ex;
        const float* ews  = edge_weight + b * Ex;
        #pragma unroll
        for (int i = 0; i < 4; i++) {
            Sd[i * 256 + t]  = dsts[i * 256 + t];
            Sew[i * 256 + t] = ews[i * 256 + t];
        }
    }
    __syncthreads();

    // ---- per-vertex bias dots: Sa[v] = X_v.u , Sc[v] = X_v.r ----
    {
        const float4 ua = ((const float4*)Su)[j];
        const float4 ub = ((const float4*)Su)[32 + j];
        const float4 ra = ((const float4*)Sr)[j];
        const float4 rb = ((const float4*)Sr)[32 + j];
        #pragma unroll
        for (int s = 0; s < 8; s++) {
            int v = w * 8 + s;
            float4 xa = *(const float4*)(Xs + v * XSTR + 4 * j);
            float4 xb = *(const float4*)(Xs + v * XSTR + 128 + 4 * j);
            float pa = xa.x*ua.x + xa.y*ua.y + xa.z*ua.z + xa.w*ua.w
                     + xb.x*ub.x + xb.y*ub.y + xb.z*ub.z + xb.w*ub.w;
            float pc = xa.x*ra.x + xa.y*ra.y + xa.z*ra.z + xa.w*ra.w
                     + xb.x*rb.x + xb.y*rb.y + xb.z*rb.z + xb.w*rb.w;
            #pragma unroll
            for (int off = 16; off > 0; off >>= 1) {
                pa += __shfl_xor_sync(~0u, pa, off);
                pc += __shfl_xor_sync(~0u, pc, off);
            }
            if (j == 0) { Sa[v] = pa; Sc[v] = pc; }
        }
    }

    // ---- GEMM 1: Z[64][256] = X @ Mt^T  (Z[v][n] = sum_k X[v][k] M[k][n]) ----
    const int rA = j >> 2, cA = j & 3;
    {
        float acc[2][8][4];
        #pragma unroll
        for (int a = 0; a < 2; a++)
            #pragma unroll
            for (int c = 0; c < 8; c++)
                #pragma unroll
                for (int q = 0; q < 4; q++) acc[a][c][q] = 0.f;

        const int mb = (w & 1) * 32;
        const int nb = (w >> 1) * 64;

        #pragma unroll 1
        for (int kt = 0; kt < 8; kt++) {
            if (kt < 7) {
                float* Wn = (kt & 1) ? Ws0 : Ws1;            // buffer for chunk kt+1
                const float* src = g_Mt + (kt + 1) * 32;
                #pragma unroll
                for (int i = 0; i < 8; i++) {
                    int idx = i * 256 + t, n = idx >> 3, q = idx & 7;
                    unsigned d = (unsigned)__cvta_generic_to_shared(Wn + n * WSTR + q * 4);
                    asm volatile("cp.async.ca.shared.global [%0], [%1], 16;"
                                 :: "r"(d), "l"(src + n * 256 + q * 4));
                }
                asm volatile("cp.async.commit_group;" ::: "memory");
                asm volatile("cp.async.wait_group 1;" ::: "memory");
            } else {
                asm volatile("cp.async.wait_group 0;" ::: "memory");
            }
            __syncthreads();
            const float* W = (kt & 1) ? Ws1 : Ws0;

            #pragma unroll
            for (int ks = 0; ks < 4; ks++) {
                const int kc = kt * 32 + ks * 8;
                unsigned a[2][4];
                #pragma unroll
                for (int mt = 0; mt < 2; mt++) {
                    const float* xp = Xs + (mb + mt * 16 + rA) * XSTR + kc + cA;
                    a[mt][0] = __float_as_uint(xp[0]);
                    a[mt][1] = __float_as_uint(xp[8 * XSTR]);
                    a[mt][2] = __float_as_uint(xp[4]);
                    a[mt][3] = __float_as_uint(xp[8 * XSTR + 4]);
                }
                #pragma unroll
                for (int nt = 0; nt < 8; nt++) {
                    const float* wp = W + (nb + nt * 8 + rA) * WSTR + ks * 8 + cA;
                    unsigned b0 = __float_as_uint(wp[0]);
                    unsigned b1 = __float_as_uint(wp[4]);
                    mma_tf32(acc[0][nt], a[0], b0, b1);
                    mma_tf32(acc[1][nt], a[1], b0, b1);
                }
            }
            __syncthreads();
        }

        // epilogue: Z to smem
        #pragma unroll
        for (int mt = 0; mt < 2; mt++)
            #pragma unroll
            for (int nt = 0; nt < 8; nt++) {
                int row = mb + mt * 16 + rA;
                int col = nb + nt * 8 + 2 * cA;
                *(float2*)(Zs + row * XSTR + col)       = make_float2(acc[mt][nt][0], acc[mt][nt][1]);
                *(float2*)(Zs + (row + 8) * XSTR + col) = make_float2(acc[mt][nt][2], acc[mt][nt][3]);
            }
    }
    __syncthreads();   // Zs complete; Ws dead from here on

    // ---- GEMM 2: S[64][64] = Z @ X^T  (S[v][dst] = x_v M x_dst^T) ----
    // warps 0-3: k in [0,128), m-block (w&3)*16 -> Ss0 ; warps 4-7: k in [128,256) -> Ss1
    {
        float sacc[8][4];
        #pragma unroll
        for (int c = 0; c < 8; c++)
            #pragma unroll
            for (int q = 0; q < 4; q++) sacc[c][q] = 0.f;

        const int smB = (w & 3) * 16;
        const int kh0 = (w >> 2) * 128;

        #pragma unroll 4
        for (int ks = 0; ks < 16; ks++) {
            const int kc = kh0 + ks * 8;
            unsigned a[4];
            const float* zp = Zs + (smB + rA) * XSTR + kc + cA;
            a[0] = __float_as_uint(zp[0]);
            a[1] = __float_as_uint(zp[8 * XSTR]);
            a[2] = __float_as_uint(zp[4]);
            a[3] = __float_as_uint(zp[8 * XSTR + 4]);
            #pragma unroll
            for (int nt = 0; nt < 8; nt++) {
                const float* xp = Xs + (nt * 8 + rA) * XSTR + kc + cA;
                unsigned b0 = __float_as_uint(xp[0]);
                unsigned b1 = __float_as_uint(xp[4]);
                mma_tf32(sacc[nt], a, b0, b1);
            }
        }

        float* SsH = (w >> 2) ? Ss1 : Ss0;
        #pragma unroll
        for (int nt = 0; nt < 8; nt++) {
            int row = smB + rA;
            int col = nt * 8 + 2 * cA;
            *(float2*)(SsH + row * SSTR + col)       = make_float2(sacc[nt][0], sacc[nt][1]);
            *(float2*)(SsH + (row + 8) * SSTR + col) = make_float2(sacc[nt][2], sacc[nt][3]);
        }
    }
    __syncthreads();

    // ---- softmax over each src's 16 neighbors; 16-lane group per src ----
    const float skip = attn_skip_p[0];
    const float c0 = g_c0;
    float* outEw = out + (size_t)2 * Bx * Ex * Lx;
    const int g  = j >> 4;     // group 0/1 within warp
    const int jj = j & 15;     // neighbor index tt

    #pragma unroll
    for (int it = 0; it < 4; it++) {
        const int v  = it * 16 + w * 2 + g;
        const int dst = Sd[v * 16 + jj];
        float sc = (Ss0[v * SSTR + dst] + Ss1[v * SSTR + dst]
                    + Sa[v] + Sc[dst] + c0) * 0.0625f;
        float m = sc;
        #pragma unroll
        for (int off = 8; off > 0; off >>= 1) m = fmaxf(m, __shfl_xor_sync(~0u, m, off));
        float e = __expf(sc - m);
        float Zt = e;
        #pragma unroll
        for (int off = 8; off > 0; off >>= 1) Zt += __shfl_xor_sync(~0u, Zt, off);
        const int ge = b * Ex + v * 16 + jj;
        outEw[(size_t)ge * Lx + l] = skip * Sew[v * 16 + jj] + (1.0f - skip) * e / Zt;
    }
}

extern "C" void kernel_launch(void* const* d_in, const int* in_sizes, int n_in,
                              void* d_out, int out_size)
{
    const float* hs = (const float*)d_in[0];
    const int*   ei = (const int*)  d_in[1];
    const float* ew = (const float*)d_in[2];
    const float* Wq = (const float*)d_in[3];
    const float* bq = (const float*)d_in[4];
    const float* Wk = (const float*)d_in[5];
    const float* bk = (const float*)d_in[6];
    const float* sk = (const float*)d_in[7];
    float* out = (float*)d_out;

    precompute_kernel<<<256, 256>>>(Wq, bq, Wk, bk);

    const int smem_bytes = (64 * XSTR * 2 + 256 * WSTR * 2 + 256 + 256 + 64 + 64 + 1024 + 1024) * 4;
    cudaFuncSetAttribute(edge_learner_main,
                         cudaFuncAttributeMaxDynamicSharedMemorySize, smem_bytes);
    edge_learner_main<<<Bx * Lx, 256, smem_bytes>>>(hs, ei, ew, sk, out);
}